// round 6
// baseline (speedup 1.0000x reference)
#include <cuda_runtime.h>

#define NQ_MAX 131072
#define E_MAX  2097152

// ---------- device scratch (no allocations allowed) ----------
__device__ __align__(16) float g_u[64];        // W^T wq
__device__ __align__(16) float g_v[64];        // W^T wk
__device__ float g_C;                          // proj_b.(wq+wk) + attend_b
__device__ __align__(16) float g_sq[NQ_MAX];   // per-query scalar
__device__ __align__(16) float g_sk[NQ_MAX];   // per-key scalar
__device__ int   g_count[NQ_MAX];
__device__ int   g_off[NQ_MAX + 1];
__device__ int   g_cursor[NQ_MAX];
__device__ int   g_bsum[1024];
__device__ __align__(16) int2  g_pair[E_MAX];  // sorted (ki, exp(logit) bits)
__device__ __align__(16) float g_kp[(size_t)NQ_MAX * 64];  // kv_proj

// ---------- kernels ----------
// zero histogram (whole grid) + compute u, v, C (block 0)
__global__ void k_prep(const float* __restrict__ W, const float* __restrict__ pb,
                       const float* __restrict__ aw, const float* __restrict__ ab,
                       int Nq) {
    int i = blockIdx.x * blockDim.x + threadIdx.x;
    if (i < Nq) g_count[i] = 0;
    if (blockIdx.x == 0) {
        int j = threadIdx.x;
        if (j < 64) {
            float uj = 0.f, vj = 0.f;
            #pragma unroll
            for (int r = 0; r < 64; r++) {
                float w = W[r * 64 + j];
                uj += w * aw[r];
                vj += w * aw[64 + r];
            }
            g_u[j] = uj;
            g_v[j] = vj;
        }
        if (j == 0) {
            float c = ab[0];
            for (int r = 0; r < 64; r++) c += pb[r] * (aw[r] + aw[64 + r]);
            g_C = c;
        }
    }
}

// warp per node row: sq = q . u  (or sk = kv . v)
__global__ void k_node_scalars(const float* __restrict__ q, const float* __restrict__ kv,
                               int Nq, int Nk) {
    int w = (blockIdx.x * blockDim.x + threadIdx.x) >> 5;
    int lane = threadIdx.x & 31;
    if (w >= Nq + Nk) return;
    const float* row; const float* wt; float* dst;
    if (w < Nq) { row = q  + (size_t)w * 64;        wt = g_u; dst = g_sq + w; }
    else        { int m = w - Nq;
                  row = kv + (size_t)m * 64;        wt = g_v; dst = g_sk + m; }
    float2 a = *(const float2*)(row + lane * 2);
    float2 b = *(const float2*)(wt  + lane * 2);
    float acc = a.x * b.x + a.y * b.y;
    #pragma unroll
    for (int o = 16; o; o >>= 1) acc += __shfl_xor_sync(0xffffffffu, acc, o);
    if (lane == 0) *dst = acc;
}

// degree histogram over qi, 4 edges per thread
__global__ void k_edge1(const int* __restrict__ eidx, int E) {
    int j4 = (blockIdx.x * blockDim.x + threadIdx.x) * 4;
    if (j4 + 3 < E) {
        int4 v = *(const int4*)(eidx + j4);
        atomicAdd(&g_count[v.x], 1);
        atomicAdd(&g_count[v.y], 1);
        atomicAdd(&g_count[v.z], 1);
        atomicAdd(&g_count[v.w], 1);
    } else {
        for (int j = j4; j < E; j++) atomicAdd(&g_count[eidx[j]], 1);
    }
}

// block-level exclusive scan (1024 threads, shuffle-based) -> g_off (local), g_bsum
__global__ void k_scan_a(int Nq) {
    __shared__ float dummy_guard;  (void)dummy_guard;
    __shared__ int wsum[32];
    int tid  = threadIdx.x;
    int lane = tid & 31;
    int wid  = tid >> 5;
    int i = blockIdx.x * 1024 + tid;
    int x = (i < Nq) ? g_count[i] : 0;
    // inclusive warp scan
    int v = x;
    #pragma unroll
    for (int o = 1; o < 32; o <<= 1) {
        int t = __shfl_up_sync(0xffffffffu, v, o);
        if (lane >= o) v += t;
    }
    if (lane == 31) wsum[wid] = v;
    __syncthreads();
    if (wid == 0) {
        int w = wsum[lane];
        #pragma unroll
        for (int o = 1; o < 32; o <<= 1) {
            int t = __shfl_up_sync(0xffffffffu, w, o);
            if (lane >= o) w += t;
        }
        wsum[lane] = w;
    }
    __syncthreads();
    int incl = v + (wid ? wsum[wid - 1] : 0);
    if (i < Nq) g_off[i] = incl - x;
    if (tid == 1023) g_bsum[blockIdx.x] = incl;
}

// fused: scan g_bsum (per-block recompute, nb <= 1024) + add to offsets + init cursor
__global__ void k_scan_c(int Nq, int E, int nb) {
    __shared__ int spref[1024];
    __shared__ int wsum[32];
    int tid = threadIdx.x;       // 256 threads
    // load and scan nb block sums using the whole block (nb <= 1024)
    for (int t = tid; t < nb; t += 256) spref[t] = g_bsum[t];
    __syncthreads();
    // simple Hillis-Steele over spref in shared (nb small -> cheap)
    for (int off = 1; off < nb; off <<= 1) {
        int t0 = (tid < nb && tid >= off) ? spref[tid - off] : 0;
        int t1 = (256 + tid < nb && 256 + tid >= off) ? spref[256 + tid - off] : 0;
        int t2 = (512 + tid < nb && 512 + tid >= off) ? spref[512 + tid - off] : 0;
        int t3 = (768 + tid < nb && 768 + tid >= off) ? spref[768 + tid - off] : 0;
        __syncthreads();
        if (tid < nb) spref[tid] += t0;
        if (256 + tid < nb) spref[256 + tid] += t1;
        if (512 + tid < nb) spref[512 + tid] += t2;
        if (768 + tid < nb) spref[768 + tid] += t3;
        __syncthreads();
    }
    (void)wsum;
    int i = blockIdx.x * blockDim.x + tid;
    if (i < Nq) {
        int b = i >> 10;
        int off = g_off[i] + (b ? spref[b - 1] : 0);
        g_off[i] = off;
        g_cursor[i] = off;
    }
    if (i == 0) g_off[Nq] = E;
}

// counting-sort scatter: compute exp(leaky(logit)), place (ki, exp) pair into
// qi-contiguous segment. 2 edges per thread for MLP on the atomic->store chain.
__global__ void k_scatter(const int* __restrict__ eidx, int E) {
    int j2 = (blockIdx.x * blockDim.x + threadIdx.x) * 2;
    if (((E & 1) == 0) && (j2 + 1 < E)) {
        int2 qq = *(const int2*)(eidx + j2);
        int2 kk = *(const int2*)(eidx + E + j2);
        float e0 = g_sq[qq.x] + g_sk[kk.x] + g_C;
        float e1 = g_sq[qq.y] + g_sk[kk.y] + g_C;
        e0 = e0 > 0.f ? e0 : 0.2f * e0;
        e1 = e1 > 0.f ? e1 : 0.2f * e1;
        e0 = __expf(e0);
        e1 = __expf(e1);
        int p0 = atomicAdd(&g_cursor[qq.x], 1);
        int p1 = atomicAdd(&g_cursor[qq.y], 1);
        g_pair[p0] = make_int2(kk.x, __float_as_int(e0));
        g_pair[p1] = make_int2(kk.y, __float_as_int(e1));
    } else {
        for (int j = j2; j < E && j < j2 + 2; j++) {
            int qi = eidx[j];
            int ki = eidx[E + j];
            float ev = g_sq[qi] + g_sk[ki] + g_C;
            ev = ev > 0.f ? ev : 0.2f * ev;
            ev = __expf(ev);
            int pos = atomicAdd(&g_cursor[qi], 1);
            g_pair[pos] = make_int2(ki, __float_as_int(ev));
        }
    }
}

// kv_proj = kv @ W^T + b   (Nk x 64), 128 rows per block
__global__ void k_gemm(const float* __restrict__ x, const float* __restrict__ W,
                       const float* __restrict__ b, int Nk) {
    __shared__ __align__(16) float Wts[64 * 64];  // Wts[j*64+i] = W[i*64+j]
    __shared__ __align__(16) float xs[16 * 64];
    int tid = threadIdx.x;
    for (int t = tid * 4; t < 4096; t += 1024) {
        float4 w = *(const float4*)(W + t);
        int i = t >> 6, j = t & 63;
        Wts[(j + 0) * 64 + i] = w.x;
        Wts[(j + 1) * 64 + i] = w.y;
        Wts[(j + 2) * 64 + i] = w.z;
        Wts[(j + 3) * 64 + i] = w.w;
    }
    int r  = tid >> 4;   // 0..15 row within tile
    int cg = tid & 15;   // 0..15 column group (4 cols)
    float4 bias = *(const float4*)(b + cg * 4);
    int base = blockIdx.x * 128;
    for (int it = 0; it < 8; it++) {
        __syncthreads();   // covers Wts on it=0, xs reuse otherwise
        int lr = tid >> 4, lj = tid & 15;
        int row_l = base + it * 16 + lr;
        float4 xv4 = (row_l < Nk) ? *(const float4*)(x + (size_t)row_l * 64 + lj * 4)
                                  : make_float4(0.f, 0.f, 0.f, 0.f);
        *(float4*)(xs + lr * 64 + lj * 4) = xv4;
        __syncthreads();
        int row = base + it * 16 + r;
        float4 acc = bias;
        #pragma unroll
        for (int j = 0; j < 64; j++) {
            float  xv = xs[r * 64 + j];
            float4 wv = *(const float4*)(Wts + j * 64 + cg * 4);
            acc.x += xv * wv.x; acc.y += xv * wv.y;
            acc.z += xv * wv.z; acc.w += xv * wv.w;
        }
        if (row < Nk) *(float4*)(g_kp + (size_t)row * 64 + cg * 4) = acc;
    }
}

// warp per query node: single pass. Pairs hold exp(logit) already (no max shift
// needed: logits are bounded, eps stays negligible). Stage (ki, exp) into shared
// so the broadcast loop uses LDS (independent iters, MLP) instead of serialized shfls.
__global__ void k_agg(float* __restrict__ out, int Nq) {
    __shared__ int   s_ki[8][32];
    __shared__ float s_ex[8][32];
    int w = (blockIdx.x * blockDim.x + threadIdx.x) >> 5;
    int wl = (threadIdx.x >> 5) & 7;
    int lane = threadIdx.x & 31;
    if (w >= Nq) return;
    int s = g_off[w], e = g_off[w + 1];
    float sum = 0.f, ax = 0.f, ay = 0.f;
    for (int base = s; base < e; base += 32) {
        int i = base + lane;
        float ex = 0.f; int kn = 0;
        if (i < e) {
            int2 p = g_pair[i];
            kn = p.x;
            ex = __int_as_float(p.y);
        }
        sum += ex;
        s_ki[wl][lane] = kn;
        s_ex[wl][lane] = ex;
        __syncwarp();
        int cnt = min(32, e - base);
        #pragma unroll 4
        for (int j = 0; j < cnt; j++) {
            float ej = s_ex[wl][j];
            int   kj = s_ki[wl][j];
            float2 v = *(const float2*)(g_kp + (size_t)kj * 64 + lane * 2);
            ax += ej * v.x;
            ay += ej * v.y;
        }
        __syncwarp();
    }
    #pragma unroll
    for (int o = 16; o; o >>= 1) sum += __shfl_xor_sync(0xffffffffu, sum, o);
    float inv = 1.0f / (sum + 1e-10f);   // EPS from reference
    *(float2*)(out + (size_t)w * 64 + lane * 2) = make_float2(ax * inv, ay * inv);
}

// ---------- launch ----------
extern "C" void kernel_launch(void* const* d_in, const int* in_sizes, int n_in,
                              void* d_out, int out_size) {
    const float* q  = (const float*)d_in[0];      // query_nodes (Nq,64)
    const float* kv = (const float*)d_in[1];      // key_value_nodes (Nk,64)
    const int*   ei = (const int*)d_in[2];        // edge_index (2,E) int32
    const float* W  = (const float*)d_in[3];      // proj_w (64,64)
    const float* pb = (const float*)d_in[4];      // proj_b (64)
    const float* aw = (const float*)d_in[5];      // attend_w (1,128)
    const float* ab = (const float*)d_in[6];      // attend_b (1)
    float* out = (float*)d_out;

    int Nq = in_sizes[0] / 64;
    int Nk = in_sizes[1] / 64;
    int E  = in_sizes[2] / 2;
    int nb = (Nq + 1023) / 1024;

    k_prep<<<(Nq + 255) / 256, 256>>>(W, pb, aw, ab, Nq);
    int nwarp = Nq + Nk;
    k_node_scalars<<<(nwarp + 7) / 8, 256>>>(q, kv, Nq, Nk);
    k_edge1<<<(E / 4 + 255) / 256, 256>>>(ei, E);
    k_scan_a<<<nb, 1024>>>(Nq);
    k_scan_c<<<(Nq + 255) / 256, 256>>>(Nq, E, nb);
    k_scatter<<<(E / 2 + 255) / 256, 256>>>(ei, E);
    k_gemm<<<(Nk + 127) / 128, 256>>>(kv, W, pb, Nk);
    k_agg<<<(Nq + 7) / 8, 256>>>(out, Nq);
}

// round 7
// speedup vs baseline: 1.4601x; 1.4601x over previous
#include <cuda_runtime.h>

#define NQ_MAX 131072
#define E_MAX  2097152

// ---------- device scratch (no allocations allowed) ----------
__device__ __align__(16) float g_u[64];        // W^T wq
__device__ __align__(16) float g_v[64];        // W^T wk
__device__ float g_C;                          // proj_b.(wq+wk) + attend_b
__device__ __align__(16) float g_sq[NQ_MAX];   // per-query scalar
__device__ __align__(16) float g_sk[NQ_MAX];   // per-key scalar
__device__ int   g_count[NQ_MAX];
__device__ int   g_off[NQ_MAX + 1];
__device__ int   g_cursor[NQ_MAX];
__device__ int   g_bsum[1024];
__device__ __align__(16) int2  g_pair[E_MAX];  // sorted (ki, exp(leaky(logit)) bits)
__device__ __align__(16) float g_kp[(size_t)NQ_MAX * 64];  // kv_proj

// ---------- kernels ----------
// zero histogram (whole grid) + compute u, v, C (block 0)
__global__ void k_prep(const float* __restrict__ W, const float* __restrict__ pb,
                       const float* __restrict__ aw, const float* __restrict__ ab,
                       int Nq) {
    int i = blockIdx.x * blockDim.x + threadIdx.x;
    if (i < Nq) g_count[i] = 0;
    if (blockIdx.x == 0) {
        int j = threadIdx.x;
        if (j < 64) {
            float uj = 0.f, vj = 0.f;
            #pragma unroll
            for (int r = 0; r < 64; r++) {
                float w = W[r * 64 + j];
                uj += w * aw[r];
                vj += w * aw[64 + r];
            }
            g_u[j] = uj;
            g_v[j] = vj;
        }
        if (j == 0) {
            float c = ab[0];
            for (int r = 0; r < 64; r++) c += pb[r] * (aw[r] + aw[64 + r]);
            g_C = c;
        }
    }
}

// warp per node row: sq = q . u  (or sk = kv . v)
__global__ void k_node_scalars(const float* __restrict__ q, const float* __restrict__ kv,
                               int Nq, int Nk) {
    int w = (blockIdx.x * blockDim.x + threadIdx.x) >> 5;
    int lane = threadIdx.x & 31;
    if (w >= Nq + Nk) return;
    const float* row; const float* wt; float* dst;
    if (w < Nq) { row = q  + (size_t)w * 64;        wt = g_u; dst = g_sq + w; }
    else        { int m = w - Nq;
                  row = kv + (size_t)m * 64;        wt = g_v; dst = g_sk + m; }
    float2 a = *(const float2*)(row + lane * 2);
    float2 b = *(const float2*)(wt  + lane * 2);
    float acc = a.x * b.x + a.y * b.y;
    #pragma unroll
    for (int o = 16; o; o >>= 1) acc += __shfl_xor_sync(0xffffffffu, acc, o);
    if (lane == 0) *dst = acc;
}

// degree histogram over qi, 4 edges per thread
__global__ void k_edge1(const int* __restrict__ eidx, int E) {
    int j4 = (blockIdx.x * blockDim.x + threadIdx.x) * 4;
    if (j4 + 3 < E) {
        int4 v = *(const int4*)(eidx + j4);
        atomicAdd(&g_count[v.x], 1);
        atomicAdd(&g_count[v.y], 1);
        atomicAdd(&g_count[v.z], 1);
        atomicAdd(&g_count[v.w], 1);
    } else {
        for (int j = j4; j < E; j++) atomicAdd(&g_count[eidx[j]], 1);
    }
}

// block-level exclusive scan (1024 threads, shuffle-based) -> g_off (local), g_bsum
__global__ void k_scan_a(int Nq) {
    __shared__ int wsum[32];
    int tid  = threadIdx.x;
    int lane = tid & 31;
    int wid  = tid >> 5;
    int i = blockIdx.x * 1024 + tid;
    int x = (i < Nq) ? g_count[i] : 0;
    int v = x;
    #pragma unroll
    for (int o = 1; o < 32; o <<= 1) {
        int t = __shfl_up_sync(0xffffffffu, v, o);
        if (lane >= o) v += t;
    }
    if (lane == 31) wsum[wid] = v;
    __syncthreads();
    if (wid == 0) {
        int w = wsum[lane];
        #pragma unroll
        for (int o = 1; o < 32; o <<= 1) {
            int t = __shfl_up_sync(0xffffffffu, w, o);
            if (lane >= o) w += t;
        }
        wsum[lane] = w;
    }
    __syncthreads();
    int incl = v + (wid ? wsum[wid - 1] : 0);
    if (i < Nq) g_off[i] = incl - x;
    if (tid == 1023) g_bsum[blockIdx.x] = incl;
}

// fused: scan g_bsum (per-block recompute, nb <= 1024) + add to offsets + init cursor
__global__ void k_scan_c(int Nq, int E, int nb) {
    __shared__ int spref[1024];
    int tid = threadIdx.x;       // 256 threads
    for (int t = tid; t < nb; t += 256) spref[t] = g_bsum[t];
    __syncthreads();
    for (int off = 1; off < nb; off <<= 1) {
        int t0 = (tid < nb && tid >= off) ? spref[tid - off] : 0;
        int t1 = (256 + tid < nb && 256 + tid >= off) ? spref[256 + tid - off] : 0;
        int t2 = (512 + tid < nb && 512 + tid >= off) ? spref[512 + tid - off] : 0;
        int t3 = (768 + tid < nb && 768 + tid >= off) ? spref[768 + tid - off] : 0;
        __syncthreads();
        if (tid < nb) spref[tid] += t0;
        if (256 + tid < nb) spref[256 + tid] += t1;
        if (512 + tid < nb) spref[512 + tid] += t2;
        if (768 + tid < nb) spref[768 + tid] += t3;
        __syncthreads();
    }
    int i = blockIdx.x * blockDim.x + tid;
    if (i < Nq) {
        int b = i >> 10;
        int off = g_off[i] + (b ? spref[b - 1] : 0);
        g_off[i] = off;
        g_cursor[i] = off;
    }
    if (i == 0) g_off[Nq] = E;
}

// counting-sort scatter: compute exp(leaky(logit)), place (ki, exp) pair into
// qi-contiguous segment. 4 edges per thread for MLP on the atomic->store chains.
__global__ void k_scatter(const int* __restrict__ eidx, int E) {
    int j4 = (blockIdx.x * blockDim.x + threadIdx.x) * 4;
    if (((E & 3) == 0) && (j4 + 3 < E)) {
        int4 qq = *(const int4*)(eidx + j4);
        int4 kk = *(const int4*)(eidx + E + j4);
        float e0 = g_sq[qq.x] + g_sk[kk.x] + g_C;
        float e1 = g_sq[qq.y] + g_sk[kk.y] + g_C;
        float e2 = g_sq[qq.z] + g_sk[kk.z] + g_C;
        float e3 = g_sq[qq.w] + g_sk[kk.w] + g_C;
        e0 = __expf(e0 > 0.f ? e0 : 0.2f * e0);
        e1 = __expf(e1 > 0.f ? e1 : 0.2f * e1);
        e2 = __expf(e2 > 0.f ? e2 : 0.2f * e2);
        e3 = __expf(e3 > 0.f ? e3 : 0.2f * e3);
        int p0 = atomicAdd(&g_cursor[qq.x], 1);
        int p1 = atomicAdd(&g_cursor[qq.y], 1);
        int p2 = atomicAdd(&g_cursor[qq.z], 1);
        int p3 = atomicAdd(&g_cursor[qq.w], 1);
        g_pair[p0] = make_int2(kk.x, __float_as_int(e0));
        g_pair[p1] = make_int2(kk.y, __float_as_int(e1));
        g_pair[p2] = make_int2(kk.z, __float_as_int(e2));
        g_pair[p3] = make_int2(kk.w, __float_as_int(e3));
    } else {
        for (int j = j4; j < E && j < j4 + 4; j++) {
            int qi = eidx[j];
            int ki = eidx[E + j];
            float ev = g_sq[qi] + g_sk[ki] + g_C;
            ev = __expf(ev > 0.f ? ev : 0.2f * ev);
            int pos = atomicAdd(&g_cursor[qi], 1);
            g_pair[pos] = make_int2(ki, __float_as_int(ev));
        }
    }
}

// kv_proj = kv @ W^T + b   (Nk x 64), 128 rows per block
__global__ void k_gemm(const float* __restrict__ x, const float* __restrict__ W,
                       const float* __restrict__ b, int Nk) {
    __shared__ __align__(16) float Wts[64 * 64];  // Wts[j*64+i] = W[i*64+j]
    __shared__ __align__(16) float xs[16 * 64];
    int tid = threadIdx.x;
    for (int t = tid * 4; t < 4096; t += 1024) {
        float4 w = *(const float4*)(W + t);
        int i = t >> 6, j = t & 63;
        Wts[(j + 0) * 64 + i] = w.x;
        Wts[(j + 1) * 64 + i] = w.y;
        Wts[(j + 2) * 64 + i] = w.z;
        Wts[(j + 3) * 64 + i] = w.w;
    }
    int r  = tid >> 4;   // 0..15 row within tile
    int cg = tid & 15;   // 0..15 column group (4 cols)
    float4 bias = *(const float4*)(b + cg * 4);
    int base = blockIdx.x * 128;
    for (int it = 0; it < 8; it++) {
        __syncthreads();
        int lr = tid >> 4, lj = tid & 15;
        int row_l = base + it * 16 + lr;
        float4 xv4 = (row_l < Nk) ? *(const float4*)(x + (size_t)row_l * 64 + lj * 4)
                                  : make_float4(0.f, 0.f, 0.f, 0.f);
        *(float4*)(xs + lr * 64 + lj * 4) = xv4;
        __syncthreads();
        int row = base + it * 16 + r;
        float4 acc = bias;
        #pragma unroll
        for (int j = 0; j < 64; j++) {
            float  xv = xs[r * 64 + j];
            float4 wv = *(const float4*)(Wts + j * 64 + cg * 4);
            acc.x += xv * wv.x; acc.y += xv * wv.y;
            acc.z += xv * wv.z; acc.w += xv * wv.w;
        }
        if (row < Nk) *(float4*)(g_kp + (size_t)row * 64 + cg * 4) = acc;
    }
}

// warp per query node: pairs hold exp already. shfl-broadcast (R5-proven),
// manually unrolled x4 so 4 independent 256B gathers are in flight per step.
__global__ void k_agg(float* __restrict__ out, int Nq) {
    int w = (blockIdx.x * blockDim.x + threadIdx.x) >> 5;
    int lane = threadIdx.x & 31;
    if (w >= Nq) return;
    int s = g_off[w], e = g_off[w + 1];
    const float2* kp_l = (const float2*)g_kp + lane;   // row k at kp_l[k*32]
    float sum = 0.f, ax = 0.f, ay = 0.f;
    for (int base = s; base < e; base += 32) {
        int i = base + lane;
        float ex = 0.f; int kn = 0;
        if (i < e) {
            int2 p = g_pair[i];
            kn = p.x;
            ex = __int_as_float(p.y);
        }
        sum += ex;
        int cnt = min(32, e - base);
        int j = 0;
        for (; j + 3 < cnt; j += 4) {
            float e0 = __shfl_sync(0xffffffffu, ex, j);
            float e1 = __shfl_sync(0xffffffffu, ex, j + 1);
            float e2 = __shfl_sync(0xffffffffu, ex, j + 2);
            float e3 = __shfl_sync(0xffffffffu, ex, j + 3);
            int   k0 = __shfl_sync(0xffffffffu, kn, j);
            int   k1 = __shfl_sync(0xffffffffu, kn, j + 1);
            int   k2 = __shfl_sync(0xffffffffu, kn, j + 2);
            int   k3 = __shfl_sync(0xffffffffu, kn, j + 3);
            float2 v0 = kp_l[k0 * 32];
            float2 v1 = kp_l[k1 * 32];
            float2 v2 = kp_l[k2 * 32];
            float2 v3 = kp_l[k3 * 32];
            ax += e0 * v0.x; ay += e0 * v0.y;
            ax += e1 * v1.x; ay += e1 * v1.y;
            ax += e2 * v2.x; ay += e2 * v2.y;
            ax += e3 * v3.x; ay += e3 * v3.y;
        }
        for (; j < cnt; j++) {
            float e0 = __shfl_sync(0xffffffffu, ex, j);
            int   k0 = __shfl_sync(0xffffffffu, kn, j);
            float2 v0 = kp_l[k0 * 32];
            ax += e0 * v0.x; ay += e0 * v0.y;
        }
    }
    #pragma unroll
    for (int o = 16; o; o >>= 1) sum += __shfl_xor_sync(0xffffffffu, sum, o);
    float inv = 1.0f / (sum + 1e-10f);   // EPS from reference
    *(float2*)(out + (size_t)w * 64 + lane * 2) = make_float2(ax * inv, ay * inv);
}

// ---------- launch ----------
extern "C" void kernel_launch(void* const* d_in, const int* in_sizes, int n_in,
                              void* d_out, int out_size) {
    const float* q  = (const float*)d_in[0];      // query_nodes (Nq,64)
    const float* kv = (const float*)d_in[1];      // key_value_nodes (Nk,64)
    const int*   ei = (const int*)d_in[2];        // edge_index (2,E) int32
    const float* W  = (const float*)d_in[3];      // proj_w (64,64)
    const float* pb = (const float*)d_in[4];      // proj_b (64)
    const float* aw = (const float*)d_in[5];      // attend_w (1,128)
    const float* ab = (const float*)d_in[6];      // attend_b (1)
    float* out = (float*)d_out;

    int Nq = in_sizes[0] / 64;
    int Nk = in_sizes[1] / 64;
    int E  = in_sizes[2] / 2;
    int nb = (Nq + 1023) / 1024;

    k_prep<<<(Nq + 255) / 256, 256>>>(W, pb, aw, ab, Nq);
    int nwarp = Nq + Nk;
    k_node_scalars<<<(nwarp + 7) / 8, 256>>>(q, kv, Nq, Nk);
    k_edge1<<<(E / 4 + 255) / 256, 256>>>(ei, E);
    k_scan_a<<<nb, 1024>>>(Nq);
    k_scan_c<<<(Nq + 255) / 256, 256>>>(Nq, E, nb);
    k_scatter<<<(E / 4 + 255) / 256, 256>>>(ei, E);
    k_gemm<<<(Nk + 127) / 128, 256>>>(kv, W, pb, Nk);
    k_agg<<<(Nq + 7) / 8, 256>>>(out, Nq);
}